// round 2
// baseline (speedup 1.0000x reference)
#include <cuda_runtime.h>
#include <cuda_bf16.h>

#define BSZ 2
#define LSEQ 2048
#define DMODEL 1024
#define NH 16
#define DH 64

// Scratch (allocation-free rule: __device__ globals)
__device__ float g_Q[(size_t)BSZ * NH * LSEQ * DH];   // [B,H,L,Dh]
__device__ float g_K[(size_t)BSZ * NH * LSEQ * DH];   // [B,H,L,Dh]
__device__ float g_V[(size_t)BSZ * NH * LSEQ * DH];   // [B,H,L,Dh]
__device__ float g_O[(size_t)BSZ * LSEQ * NH * DH];   // [B,L,H,Dh]

// ---------------------------------------------------------------------------
// Fused QKV projection: X[4096,1024] x W*[1024,1024] -> Q/K/V [B,H,L,Dh]
// BM=BN=64, BK=16, 256 threads, 4x4 per-thread tile, 3 accumulators.
// ---------------------------------------------------------------------------
__global__ __launch_bounds__(256) void qkv_kernel(
    const float* __restrict__ x,
    const float* __restrict__ Wq,
    const float* __restrict__ Wk,
    const float* __restrict__ Wv)
{
    __shared__ __align__(16) float As[16][68];   // [kk][row] (transposed)
    __shared__ __align__(16) float Bqs[16][68];  // [kk][col]
    __shared__ __align__(16) float Bks[16][68];
    __shared__ __align__(16) float Bvs[16][68];

    const int tx = threadIdx.x, ty = threadIdx.y;
    const int tid = ty * 16 + tx;
    const int row0 = blockIdx.y * 64;
    const int col0 = blockIdx.x * 64;

    float accQ[4][4] = {}, accK[4][4] = {}, accV[4][4] = {};

    const int lr  = tid >> 2;          // 0..63 (A row)
    const int lk  = (tid & 3) * 4;     // 0..12 (A k offset)
    const int lkr = tid >> 4;          // 0..15 (B k row)
    const int lc  = (tid & 15) * 4;    // 0..60 (B col offset)

    for (int k0 = 0; k0 < DMODEL; k0 += 16) {
        float4 av = *(const float4*)(x + (size_t)(row0 + lr) * DMODEL + k0 + lk);
        As[lk + 0][lr] = av.x;
        As[lk + 1][lr] = av.y;
        As[lk + 2][lr] = av.z;
        As[lk + 3][lr] = av.w;

        *(float4*)&Bqs[lkr][lc] = *(const float4*)(Wq + (size_t)(k0 + lkr) * DMODEL + col0 + lc);
        *(float4*)&Bks[lkr][lc] = *(const float4*)(Wk + (size_t)(k0 + lkr) * DMODEL + col0 + lc);
        *(float4*)&Bvs[lkr][lc] = *(const float4*)(Wv + (size_t)(k0 + lkr) * DMODEL + col0 + lc);
        __syncthreads();

        #pragma unroll
        for (int kk = 0; kk < 16; kk++) {
            float4 a4 = *(const float4*)&As[kk][ty * 4];
            float4 q4 = *(const float4*)&Bqs[kk][tx * 4];
            float4 k4 = *(const float4*)&Bks[kk][tx * 4];
            float4 v4 = *(const float4*)&Bvs[kk][tx * 4];
            float a[4] = {a4.x, a4.y, a4.z, a4.w};
            float bq[4] = {q4.x, q4.y, q4.z, q4.w};
            float bk[4] = {k4.x, k4.y, k4.z, k4.w};
            float bv[4] = {v4.x, v4.y, v4.z, v4.w};
            #pragma unroll
            for (int i = 0; i < 4; i++) {
                #pragma unroll
                for (int j = 0; j < 4; j++) {
                    accQ[i][j] += a[i] * bq[j];
                    accK[i][j] += a[i] * bk[j];
                    accV[i][j] += a[i] * bv[j];
                }
            }
        }
        __syncthreads();
    }

    // Write out. One N-tile spans exactly one head (col0 multiple of 64).
    const int h = col0 >> 6;
    #pragma unroll
    for (int i = 0; i < 4; i++) {
        const int m = row0 + ty * 4 + i;       // global row = b*L + l
        const int b = m >> 11;                  // L = 2048
        const int l = m & (LSEQ - 1);
        const size_t base = (((size_t)b * NH + h) * LSEQ + l) * DH + tx * 4;
        *(float4*)(g_Q + base) = make_float4(accQ[i][0], accQ[i][1], accQ[i][2], accQ[i][3]);
        *(float4*)(g_K + base) = make_float4(accK[i][0], accK[i][1], accK[i][2], accK[i][3]);
        *(float4*)(g_V + base) = make_float4(accV[i][0], accV[i][1], accV[i][2], accV[i][3]);
    }
}

// ---------------------------------------------------------------------------
// Flash attention forward (causal), 64 q-rows x Dh=64 per block, K-tiles of 64.
// 256 threads (16x16), online softmax. Dynamic smem: 4 x 64x65 tiles + rows.
// ---------------------------------------------------------------------------
__global__ __launch_bounds__(256) void attn_kernel()
{
    extern __shared__ float sm[];
    float* Qs = sm;                 // [64][65]
    float* Ks = Qs + 64 * 65;       // [64][65]  (key-major: [k][d])
    float* Vs = Ks + 64 * 65;       // [64][65]  ([k][d])
    float* Ps = Vs + 64 * 65;       // [64][65]
    float* row_m = Ps + 64 * 65;    // [64]
    float* row_l = row_m + 64;      // [64]

    const int tx = threadIdx.x, ty = threadIdx.y;
    const int tid = ty * 16 + tx;
    const int qt = blockIdx.x;      // q tile 0..31
    const int h  = blockIdx.y;
    const int b  = blockIdx.z;
    const int q0 = qt * 64;

    const float* Qg = g_Q + (((size_t)b * NH + h) * LSEQ) * DH;
    const float* Kg = g_K + (((size_t)b * NH + h) * LSEQ) * DH;
    const float* Vg = g_V + (((size_t)b * NH + h) * LSEQ) * DH;

    // Load Q tile
    for (int i = tid; i < 64 * 64; i += 256) {
        int r = i >> 6, c = i & 63;
        Qs[r * 65 + c] = Qg[(size_t)(q0 + r) * DH + c];
    }
    if (tid < 64) { row_m[tid] = -1e30f; row_l[tid] = 0.0f; }

    float acc[4][4] = {};

    for (int j = 0; j <= qt; j++) {
        __syncthreads();  // protect Ks/Vs/Ps from previous iteration
        const int k0 = j * 64;
        for (int i = tid; i < 64 * 64; i += 256) {
            int r = i >> 6, c = i & 63;
            Ks[r * 65 + c] = Kg[(size_t)(k0 + r) * DH + c];
            Vs[r * 65 + c] = Vg[(size_t)(k0 + r) * DH + c];
        }
        __syncthreads();

        // S = Q * K^T   (4x4 per thread)
        float s[4][4] = {};
        #pragma unroll 16
        for (int kk = 0; kk < 64; kk++) {
            float a[4], bb[4];
            #pragma unroll
            for (int i2 = 0; i2 < 4; i2++) a[i2] = Qs[(ty * 4 + i2) * 65 + kk];
            #pragma unroll
            for (int j2 = 0; j2 < 4; j2++) bb[j2] = Ks[(tx * 4 + j2) * 65 + kk];
            #pragma unroll
            for (int i2 = 0; i2 < 4; i2++)
                #pragma unroll
                for (int j2 = 0; j2 < 4; j2++)
                    s[i2][j2] += a[i2] * bb[j2];
        }

        // scale + causal mask (only the diagonal tile has masked entries)
        const bool diag = (j == qt);
        #pragma unroll
        for (int i2 = 0; i2 < 4; i2++)
            #pragma unroll
            for (int j2 = 0; j2 < 4; j2++) {
                float v = s[i2][j2] * 0.125f;  // 1/sqrt(64)
                if (diag && (tx * 4 + j2 > ty * 4 + i2)) v = -1e30f;
                s[i2][j2] = v;
            }

        // Online softmax: rows ty*4+i2, reduced across the 16 tx lanes (in-warp)
        #pragma unroll
        for (int i2 = 0; i2 < 4; i2++) {
            const int r = ty * 4 + i2;
            float m = fmaxf(fmaxf(s[i2][0], s[i2][1]), fmaxf(s[i2][2], s[i2][3]));
            #pragma unroll
            for (int off = 8; off >= 1; off >>= 1)
                m = fmaxf(m, __shfl_xor_sync(0xffffffffu, m, off));
            const float mold = row_m[r];
            const float mnew = fmaxf(mold, m);
            float p[4], lsum = 0.0f;
            #pragma unroll
            for (int j2 = 0; j2 < 4; j2++) { p[j2] = __expf(s[i2][j2] - mnew); lsum += p[j2]; }
            #pragma unroll
            for (int off = 8; off >= 1; off >>= 1)
                lsum += __shfl_xor_sync(0xffffffffu, lsum, off);
            const float scale = __expf(mold - mnew);
            if (tx == 0) { row_m[r] = mnew; row_l[r] = row_l[r] * scale + lsum; }
            #pragma unroll
            for (int j2 = 0; j2 < 4; j2++) acc[i2][j2] *= scale;
            #pragma unroll
            for (int j2 = 0; j2 < 4; j2++) Ps[r * 65 + tx * 4 + j2] = p[j2];
        }
        __syncthreads();

        // O += P * V
        #pragma unroll 16
        for (int kk = 0; kk < 64; kk++) {
            float a[4], bb[4];
            #pragma unroll
            for (int i2 = 0; i2 < 4; i2++) a[i2] = Ps[(ty * 4 + i2) * 65 + kk];
            #pragma unroll
            for (int j2 = 0; j2 < 4; j2++) bb[j2] = Vs[kk * 65 + tx * 4 + j2];
            #pragma unroll
            for (int i2 = 0; i2 < 4; i2++)
                #pragma unroll
                for (int j2 = 0; j2 < 4; j2++)
                    acc[i2][j2] += a[i2] * bb[j2];
        }
    }
    __syncthreads();

    // Epilogue: O[b, l, h, e] = acc / row_l
    float* Og = g_O + ((size_t)b * LSEQ) * (NH * DH) + h * DH;
    #pragma unroll
    for (int i2 = 0; i2 < 4; i2++) {
        const int r = ty * 4 + i2;
        const float inv = 1.0f / row_l[r];
        #pragma unroll
        for (int j2 = 0; j2 < 4; j2++)
            Og[(size_t)(q0 + r) * (NH * DH) + tx * 4 + j2] = acc[i2][j2] * inv;
    }
}

// ---------------------------------------------------------------------------
// Output projection: g_O[4096,1024] x Wout[1024,1024] -> out[4096,1024]
// ---------------------------------------------------------------------------
__global__ __launch_bounds__(256) void oproj_kernel(
    const float* __restrict__ Wout,
    float* __restrict__ out)
{
    __shared__ __align__(16) float As[16][68];  // [kk][row]
    __shared__ __align__(16) float Bs[16][68];  // [kk][col]

    const int tx = threadIdx.x, ty = threadIdx.y;
    const int tid = ty * 16 + tx;
    const int row0 = blockIdx.y * 64;
    const int col0 = blockIdx.x * 64;

    float acc[4][4] = {};

    const int lr  = tid >> 2;
    const int lk  = (tid & 3) * 4;
    const int lkr = tid >> 4;
    const int lc  = (tid & 15) * 4;

    const float* A = g_O;  // [4096,1024] row-major view of [B,L,H,Dh]

    for (int k0 = 0; k0 < DMODEL; k0 += 16) {
        float4 av = *(const float4*)(A + (size_t)(row0 + lr) * DMODEL + k0 + lk);
        As[lk + 0][lr] = av.x;
        As[lk + 1][lr] = av.y;
        As[lk + 2][lr] = av.z;
        As[lk + 3][lr] = av.w;
        *(float4*)&Bs[lkr][lc] = *(const float4*)(Wout + (size_t)(k0 + lkr) * DMODEL + col0 + lc);
        __syncthreads();

        #pragma unroll
        for (int kk = 0; kk < 16; kk++) {
            float4 a4 = *(const float4*)&As[kk][ty * 4];
            float4 b4 = *(const float4*)&Bs[kk][tx * 4];
            float a[4] = {a4.x, a4.y, a4.z, a4.w};
            float bb[4] = {b4.x, b4.y, b4.z, b4.w};
            #pragma unroll
            for (int i = 0; i < 4; i++)
                #pragma unroll
                for (int j = 0; j < 4; j++)
                    acc[i][j] += a[i] * bb[j];
        }
        __syncthreads();
    }

    #pragma unroll
    for (int i = 0; i < 4; i++) {
        const int m = row0 + ty * 4 + i;
        *(float4*)(out + (size_t)m * DMODEL + col0 + tx * 4) =
            make_float4(acc[i][0], acc[i][1], acc[i][2], acc[i][3]);
    }
}

// ---------------------------------------------------------------------------
extern "C" void kernel_launch(void* const* d_in, const int* in_sizes, int n_in,
                              void* d_out, int out_size)
{
    const float* x    = (const float*)d_in[0];
    const float* Wq   = (const float*)d_in[1];
    const float* Wk   = (const float*)d_in[2];
    const float* Wv   = (const float*)d_in[3];
    const float* Wout = (const float*)d_in[4];
    float* out = (float*)d_out;

    dim3 blk(16, 16);

    // 1) QKV projection: grid over (N tiles = 16, M tiles = 64)
    qkv_kernel<<<dim3(16, 64), blk>>>(x, Wq, Wk, Wv);

    // 2) Flash attention: (q-tiles=32, H=16, B=2)
    const size_t attn_smem = (size_t)(4 * 64 * 65 + 128) * sizeof(float);
    cudaFuncSetAttribute(attn_kernel, cudaFuncAttributeMaxDynamicSharedMemorySize,
                         (int)attn_smem);
    attn_kernel<<<dim3(32, 16, 2), blk, attn_smem>>>();

    // 3) Output projection
    oproj_kernel<<<dim3(16, 64), blk>>>(Wout, out);
}

// round 4
// speedup vs baseline: 2.0988x; 2.0988x over previous
#include <cuda_runtime.h>
#include <cuda_bf16.h>

#define LSEQ 2048
#define DMODEL 1024
#define NTOK 4096
#define NH 16
#define DH 64
typedef __nv_bfloat16 bf16;
typedef __nv_bfloat162 bf162;

// ---------------- device scratch ----------------
__device__ bf16 g_Xhi[(size_t)NTOK * DMODEL], g_Xlo[(size_t)NTOK * DMODEL];
__device__ bf16 g_Wth[4][(size_t)DMODEL * DMODEL], g_Wtl[4][(size_t)DMODEL * DMODEL];
__device__ bf16 g_Qhi[(size_t)NTOK * DMODEL], g_Qlo[(size_t)NTOK * DMODEL];
__device__ bf16 g_Khi[(size_t)NTOK * DMODEL], g_Klo[(size_t)NTOK * DMODEL];
__device__ bf16 g_Vth[(size_t)NTOK * DMODEL], g_Vtl[(size_t)NTOK * DMODEL]; // [B,H,Dh,L]
__device__ bf16 g_Ohi[(size_t)NTOK * DMODEL], g_Olo[(size_t)NTOK * DMODEL];

// ---------------- helpers ----------------
__device__ __forceinline__ unsigned ldu(const bf16* p) {
    return *reinterpret_cast<const unsigned*>(p);
}
__device__ __forceinline__ void split2u(float x, float y, unsigned& uh, unsigned& ul) {
    bf162 h, l;
    h.x = __float2bfloat16(x); h.y = __float2bfloat16(y);
    l.x = __float2bfloat16(x - __bfloat162float(h.x));
    l.y = __float2bfloat16(y - __bfloat162float(h.y));
    uh = *reinterpret_cast<unsigned*>(&h);
    ul = *reinterpret_cast<unsigned*>(&l);
}
__device__ __forceinline__ void mma16(float* c, const unsigned* a, const unsigned* b) {
    asm volatile(
        "mma.sync.aligned.m16n8k16.row.col.f32.bf16.bf16.f32 "
        "{%0,%1,%2,%3},{%4,%5,%6,%7},{%8,%9},{%0,%1,%2,%3};"
        : "+f"(c[0]), "+f"(c[1]), "+f"(c[2]), "+f"(c[3])
        : "r"(a[0]), "r"(a[1]), "r"(a[2]), "r"(a[3]), "r"(b[0]), "r"(b[1]));
}
__device__ __forceinline__ void cpa(bf16* s, const bf16* g) {
    unsigned sa = (unsigned)__cvta_generic_to_shared(s);
    asm volatile("cp.async.cg.shared.global [%0], [%1], 16;" :: "r"(sa), "l"(g));
}
#define CP_COMMIT() asm volatile("cp.async.commit_group;")
__device__ __forceinline__ void cp_wait1() { asm volatile("cp.async.wait_group 1;"); }
__device__ __forceinline__ void cp_wait0() { asm volatile("cp.async.wait_group 0;"); }

// ---------------- split X ----------------
__global__ __launch_bounds__(256) void split_x(const float* __restrict__ src) {
    int i = blockIdx.x * 256 + threadIdx.x;
    float2 v = reinterpret_cast<const float2*>(src)[i];
    unsigned uh, ul;
    split2u(v.x, v.y, uh, ul);
    reinterpret_cast<unsigned*>(g_Xhi)[i] = uh;
    reinterpret_cast<unsigned*>(g_Xlo)[i] = ul;
}

// ---------------- transpose+split weight [K][N] -> Wt[N][K] ----------------
__global__ __launch_bounds__(256) void tsplit(const float* __restrict__ W, int wsel) {
    __shared__ float t[32][33];
    const int n0 = blockIdx.x * 32, k0 = blockIdx.y * 32;
    const int tx = threadIdx.x & 31, ty = threadIdx.x >> 5;
    #pragma unroll
    for (int i = 0; i < 4; i++)
        t[ty + i * 8][tx] = W[(size_t)(k0 + ty + i * 8) * DMODEL + n0 + tx];
    __syncthreads();
    bf16* th = g_Wth[wsel];
    bf16* tl = g_Wtl[wsel];
    #pragma unroll
    for (int i = 0; i < 4; i++) {
        int n = ty + i * 8;
        float v = t[tx][n];
        bf16 h = __float2bfloat16(v);
        th[(size_t)(n0 + n) * DMODEL + k0 + tx] = h;
        tl[(size_t)(n0 + n) * DMODEL + k0 + tx] = __float2bfloat16(v - __bfloat162float(h));
    }
}

// ---------------- bf16x3 GEMM: C[4096][1024] = A * Bt^T ----------------
// 128x128x32 tiles, 256 thr, 8 warps (2Mx4N), warp 64x32.
// MODE 0: f32 out [M][N]; MODE 1: split out [B,H,L,Dh] (osel 0=Q,1=K); MODE 2: split transposed Vt.
#define ASTR 40
#define STAGE (4 * 128 * ASTR)

template <int MODE>
__global__ __launch_bounds__(256) void gemm_kernel(int asel, int wsel, int osel,
                                                   float* __restrict__ Cf) {
    extern __shared__ __align__(16) bf16 sm[];
    const bf16* Ah = asel ? g_Ohi : g_Xhi;
    const bf16* Al = asel ? g_Olo : g_Xlo;
    const bf16* Bh = g_Wth[wsel];
    const bf16* Bl = g_Wtl[wsel];

    const int tid = threadIdx.x, lane = tid & 31, wid = tid >> 5;
    const int r = lane >> 2, q = lane & 3;
    const int wm = (wid & 1) * 64, wn = (wid >> 1) * 32;
    const int row0 = blockIdx.y * 128, col0 = blockIdx.x * 128;

    float acc[4][4][4] = {};

    auto load = [&](int k0, int st) {
        bf16* sb = sm + st * STAGE;
        #pragma unroll
        for (int i = 0; i < 2; i++) {
            int idx = tid * 2 + i;
            int rr = idx >> 2, c = idx & 3;
            const bf16* ga = Ah + (size_t)(row0 + rr) * DMODEL + k0 + c * 8;
            const bf16* gal = Al + (size_t)(row0 + rr) * DMODEL + k0 + c * 8;
            const bf16* gb = Bh + (size_t)(col0 + rr) * DMODEL + k0 + c * 8;
            const bf16* gbl = Bl + (size_t)(col0 + rr) * DMODEL + k0 + c * 8;
            cpa(sb + rr * ASTR + c * 8, ga);
            cpa(sb + 128 * ASTR + rr * ASTR + c * 8, gal);
            cpa(sb + 2 * 128 * ASTR + rr * ASTR + c * 8, gb);
            cpa(sb + 3 * 128 * ASTR + rr * ASTR + c * 8, gbl);
        }
    };

    load(0, 0); CP_COMMIT();
    load(32, 1); CP_COMMIT();

    for (int kt = 0; kt < 32; kt++) {
        if (kt < 31) cp_wait1(); else cp_wait0();
        __syncthreads();
        const int st = kt & 1;
        const bf16* ah = sm + st * STAGE + wm * ASTR;
        const bf16* al = ah + 128 * ASTR;
        const bf16* bh = sm + st * STAGE + 2 * 128 * ASTR + wn * ASTR;
        const bf16* bl = bh + 128 * ASTR;
        #pragma unroll
        for (int ks = 0; ks < 2; ks++) {
            const int ko = ks * 16 + 2 * q;
            unsigned afh[4][4], afl[4][4];
            #pragma unroll
            for (int mt = 0; mt < 4; mt++) {
                const bf16* p = ah + (mt * 16 + r) * ASTR + ko;
                const bf16* pl = al + (mt * 16 + r) * ASTR + ko;
                afh[mt][0] = ldu(p);            afh[mt][1] = ldu(p + 8 * ASTR);
                afh[mt][2] = ldu(p + 8);        afh[mt][3] = ldu(p + 8 * ASTR + 8);
                afl[mt][0] = ldu(pl);           afl[mt][1] = ldu(pl + 8 * ASTR);
                afl[mt][2] = ldu(pl + 8);       afl[mt][3] = ldu(pl + 8 * ASTR + 8);
            }
            #pragma unroll
            for (int nt = 0; nt < 4; nt++) {
                const bf16* p = bh + (nt * 8 + r) * ASTR + ko;
                const bf16* pl = bl + (nt * 8 + r) * ASTR + ko;
                unsigned bfh[2] = { ldu(p), ldu(p + 8) };
                unsigned bfl[2] = { ldu(pl), ldu(pl + 8) };
                #pragma unroll
                for (int mt = 0; mt < 4; mt++) {
                    mma16(acc[mt][nt], afh[mt], bfh);
                    mma16(acc[mt][nt], afh[mt], bfl);
                    mma16(acc[mt][nt], afl[mt], bfh);
                }
            }
        }
        __syncthreads();
        if (kt + 2 < 32) { load((kt + 2) * 32, st); CP_COMMIT(); }
    }

    // epilogue
    #pragma unroll
    for (int mt = 0; mt < 4; mt++) {
        #pragma unroll
        for (int nt = 0; nt < 4; nt++) {
            const int m = row0 + wm + mt * 16 + r;
            const int n = col0 + wn + nt * 8 + 2 * q;
            if (MODE == 0) {
                *reinterpret_cast<float2*>(Cf + (size_t)m * DMODEL + n) =
                    make_float2(acc[mt][nt][0], acc[mt][nt][1]);
                *reinterpret_cast<float2*>(Cf + (size_t)(m + 8) * DMODEL + n) =
                    make_float2(acc[mt][nt][2], acc[mt][nt][3]);
            } else {
                const int b = m >> 11, l = m & (LSEQ - 1);
                const int h = n >> 6, e = n & 63;
                unsigned h01, l01, h23, l23;
                split2u(acc[mt][nt][0], acc[mt][nt][1], h01, l01);
                split2u(acc[mt][nt][2], acc[mt][nt][3], h23, l23);
                if (MODE == 1) {
                    bf16* Ch = osel ? g_Khi : g_Qhi;
                    bf16* Cl = osel ? g_Klo : g_Qlo;
                    size_t a0 = ((((size_t)b * NH + h) * LSEQ + l) * DH + e) >> 1;
                    size_t a1 = ((((size_t)b * NH + h) * LSEQ + l + 8) * DH + e) >> 1;
                    reinterpret_cast<unsigned*>(Ch)[a0] = h01;
                    reinterpret_cast<unsigned*>(Cl)[a0] = l01;
                    reinterpret_cast<unsigned*>(Ch)[a1] = h23;
                    reinterpret_cast<unsigned*>(Cl)[a1] = l23;
                } else {
                    bf162 H01 = *reinterpret_cast<bf162*>(&h01);
                    bf162 L01 = *reinterpret_cast<bf162*>(&l01);
                    bf162 H23 = *reinterpret_cast<bf162*>(&h23);
                    bf162 L23 = *reinterpret_cast<bf162*>(&l23);
                    size_t base = (((size_t)b * NH + h) * DH + e) * LSEQ + l;
                    g_Vth[base] = H01.x;           g_Vtl[base] = L01.x;
                    g_Vth[base + LSEQ] = H01.y;    g_Vtl[base + LSEQ] = L01.y;
                    g_Vth[base + 8] = H23.x;       g_Vtl[base + 8] = L23.x;
                    g_Vth[base + LSEQ + 8] = H23.y;g_Vtl[base + LSEQ + 8] = L23.y;
                }
            }
        }
    }
}

// ---------------- flash attention (bf16x3 tensor core) ----------------
// 128 q rows/block, 8 warps x 16 rows, kv tiles of 64.
__global__ __launch_bounds__(256) void attn_kernel() {
    __shared__ __align__(16) bf16 sKh[64 * 72], sKl[64 * 72], sVh[64 * 72], sVl[64 * 72];

    const int tid = threadIdx.x, lane = tid & 31, wid = tid >> 5;
    const int r = lane >> 2, q = lane & 3;
    const int qt = blockIdx.x, h = blockIdx.y, b = blockIdx.z;
    const int q0 = qt * 128, wm = wid * 16;
    const int rowg0 = q0 + wm + r, rowg1 = rowg0 + 8;

    const bf16* Qh = g_Qhi + ((size_t)(b * NH + h) * LSEQ) * DH;
    const bf16* Ql = g_Qlo + ((size_t)(b * NH + h) * LSEQ) * DH;
    const bf16* Kh = g_Khi + ((size_t)(b * NH + h) * LSEQ) * DH;
    const bf16* Kl = g_Klo + ((size_t)(b * NH + h) * LSEQ) * DH;
    const bf16* Vh = g_Vth + ((size_t)(b * NH + h) * DH) * LSEQ;
    const bf16* Vl = g_Vtl + ((size_t)(b * NH + h) * DH) * LSEQ;

    // Q fragments (register resident)
    unsigned qh[4][4], ql[4][4];
    #pragma unroll
    for (int kk = 0; kk < 4; kk++) {
        const bf16* p = Qh + (size_t)rowg0 * DH + kk * 16 + 2 * q;
        const bf16* pl = Ql + (size_t)rowg0 * DH + kk * 16 + 2 * q;
        qh[kk][0] = ldu(p);           qh[kk][1] = ldu(p + 8 * DH);
        qh[kk][2] = ldu(p + 8);       qh[kk][3] = ldu(p + 8 * DH + 8);
        ql[kk][0] = ldu(pl);          ql[kk][1] = ldu(pl + 8 * DH);
        ql[kk][2] = ldu(pl + 8);      ql[kk][3] = ldu(pl + 8 * DH + 8);
    }

    float oacc[8][4] = {};
    float m0 = -1e30f, m1 = -1e30f, l0 = 0.f, l1 = 0.f;
    const int njv = 2 * qt + 2;

    for (int j = 0; j < njv; j++) {
        const int k0 = j * 64;
        __syncthreads();
        #pragma unroll
        for (int t = 0; t < 2; t++) {
            int idx = tid * 2 + t;
            int rr = idx >> 3, c = (idx & 7) * 8;
            cpa(sKh + rr * 72 + c, Kh + (size_t)(k0 + rr) * DH + c);
            cpa(sKl + rr * 72 + c, Kl + (size_t)(k0 + rr) * DH + c);
            cpa(sVh + rr * 72 + c, Vh + (size_t)rr * LSEQ + k0 + c);
            cpa(sVl + rr * 72 + c, Vl + (size_t)rr * LSEQ + k0 + c);
        }
        CP_COMMIT();
        cp_wait0();
        __syncthreads();

        if (k0 > q0 + wm + 15) continue;  // fully masked for this warp

        // S = Q K^T (16 x 64)
        float sacc[8][4] = {};
        #pragma unroll
        for (int nt = 0; nt < 8; nt++) {
            #pragma unroll
            for (int kk = 0; kk < 4; kk++) {
                const bf16* p = sKh + (nt * 8 + r) * 72 + kk * 16 + 2 * q;
                const bf16* pl = sKl + (nt * 8 + r) * 72 + kk * 16 + 2 * q;
                unsigned bh2[2] = { ldu(p), ldu(p + 8) };
                unsigned bl2[2] = { ldu(pl), ldu(pl + 8) };
                mma16(sacc[nt], qh[kk], bh2);
                mma16(sacc[nt], qh[kk], bl2);
                mma16(sacc[nt], ql[kk], bh2);
            }
        }

        // scale + causal mask
        #pragma unroll
        for (int nt = 0; nt < 8; nt++) {
            const int c0 = k0 + nt * 8 + 2 * q, c1 = c0 + 1;
            sacc[nt][0] = (c0 > rowg0) ? -1e30f : sacc[nt][0] * 0.125f;
            sacc[nt][1] = (c1 > rowg0) ? -1e30f : sacc[nt][1] * 0.125f;
            sacc[nt][2] = (c0 > rowg1) ? -1e30f : sacc[nt][2] * 0.125f;
            sacc[nt][3] = (c1 > rowg1) ? -1e30f : sacc[nt][3] * 0.125f;
        }

        // online softmax (rows r and r+8, reduce over 4 q-lanes)
        float mx0 = -1e30f, mx1 = -1e30f;
        #pragma unroll
        for (int nt = 0; nt < 8; nt++) {
            mx0 = fmaxf(mx0, fmaxf(sacc[nt][0], sacc[nt][1]));
            mx1 = fmaxf(mx1, fmaxf(sacc[nt][2], sacc[nt][3]));
        }
        #pragma unroll
        for (int off = 1; off <= 2; off <<= 1) {
            mx0 = fmaxf(mx0, __shfl_xor_sync(0xffffffffu, mx0, off));
            mx1 = fmaxf(mx1, __shfl_xor_sync(0xffffffffu, mx1, off));
        }
        const float mn0 = fmaxf(m0, mx0), mn1 = fmaxf(m1, mx1);
        const float es0 = __expf(m0 - mn0), es1 = __expf(m1 - mn1);
        float ls0 = 0.f, ls1 = 0.f;
        #pragma unroll
        for (int nt = 0; nt < 8; nt++) {
            sacc[nt][0] = __expf(sacc[nt][0] - mn0);
            sacc[nt][1] = __expf(sacc[nt][1] - mn0);
            sacc[nt][2] = __expf(sacc[nt][2] - mn1);
            sacc[nt][3] = __expf(sacc[nt][3] - mn1);
            ls0 += sacc[nt][0] + sacc[nt][1];
            ls1 += sacc[nt][2] + sacc[nt][3];
        }
        #pragma unroll
        for (int off = 1; off <= 2; off <<= 1) {
            ls0 += __shfl_xor_sync(0xffffffffu, ls0, off);
            ls1 += __shfl_xor_sync(0xffffffffu, ls1, off);
        }
        m0 = mn0; m1 = mn1;
        l0 = l0 * es0 + ls0;
        l1 = l1 * es1 + ls1;
        #pragma unroll
        for (int nt = 0; nt < 8; nt++) {
            oacc[nt][0] *= es0; oacc[nt][1] *= es0;
            oacc[nt][2] *= es1; oacc[nt][3] *= es1;
        }

        // O += P V  (P fragments assembled from sacc registers)
        #pragma unroll
        for (int kk = 0; kk < 4; kk++) {
            unsigned pah[4], pal[4];
            split2u(sacc[2*kk][0],   sacc[2*kk][1],   pah[0], pal[0]);
            split2u(sacc[2*kk][2],   sacc[2*kk][3],   pah[1], pal[1]);
            split2u(sacc[2*kk+1][0], sacc[2*kk+1][1], pah[2], pal[2]);
            split2u(sacc[2*kk+1][2], sacc[2*kk+1][3], pah[3], pal[3]);
            #pragma unroll
            for (int nt = 0; nt < 8; nt++) {
                const bf16* p = sVh + (nt * 8 + r) * 72 + kk * 16 + 2 * q;
                const bf16* pl = sVl + (nt * 8 + r) * 72 + kk * 16 + 2 * q;
                unsigned bh2[2] = { ldu(p), ldu(p + 8) };
                unsigned bl2[2] = { ldu(pl), ldu(pl + 8) };
                mma16(oacc[nt], pah, bh2);
                mma16(oacc[nt], pah, bl2);
                mma16(oacc[nt], pal, bh2);
            }
        }
    }

    // epilogue: O/l -> split bf16 [B,L,H,Dh]
    const float i0 = 1.f / l0, i1 = 1.f / l1;
    #pragma unroll
    for (int nt = 0; nt < 8; nt++) {
        unsigned h01, l01, h23, l23;
        split2u(oacc[nt][0] * i0, oacc[nt][1] * i0, h01, l01);
        split2u(oacc[nt][2] * i1, oacc[nt][3] * i1, h23, l23);
        const int e = nt * 8 + 2 * q;
        size_t a0 = (((size_t)(b * LSEQ + rowg0) * NH + h) * DH + e) >> 1;
        size_t a1 = (((size_t)(b * LSEQ + rowg1) * NH + h) * DH + e) >> 1;
        reinterpret_cast<unsigned*>(g_Ohi)[a0] = h01;
        reinterpret_cast<unsigned*>(g_Olo)[a0] = l01;
        reinterpret_cast<unsigned*>(g_Ohi)[a1] = h23;
        reinterpret_cast<unsigned*>(g_Olo)[a1] = l23;
    }
}

// ---------------------------------------------------------------------------
extern "C" void kernel_launch(void* const* d_in, const int* in_sizes, int n_in,
                              void* d_out, int out_size)
{
    const float* x = (const float*)d_in[0];
    float* out = (float*)d_out;

    const int gsm = 2 * STAGE * (int)sizeof(bf16);  // 80KB
    cudaFuncSetAttribute(gemm_kernel<0>, cudaFuncAttributeMaxDynamicSharedMemorySize, gsm);
    cudaFuncSetAttribute(gemm_kernel<1>, cudaFuncAttributeMaxDynamicSharedMemorySize, gsm);
    cudaFuncSetAttribute(gemm_kernel<2>, cudaFuncAttributeMaxDynamicSharedMemorySize, gsm);

    split_x<<<NTOK * DMODEL / 512, 256>>>(x);
    for (int w = 0; w < 4; w++)
        tsplit<<<dim3(32, 32), 256>>>((const float*)d_in[1 + w], w);

    dim3 gg(8, 32);
    gemm_kernel<1><<<gg, 256, gsm>>>(0, 0, 0, nullptr);  // Q
    gemm_kernel<1><<<gg, 256, gsm>>>(0, 1, 1, nullptr);  // K
    gemm_kernel<2><<<gg, 256, gsm>>>(0, 2, 0, nullptr);  // V (transposed)

    attn_kernel<<<dim3(LSEQ / 128, NH, 2), 256>>>();

    gemm_kernel<0><<<gg, 256, gsm>>>(1, 3, 0, out);      // out projection
}